// round 17
// baseline (speedup 1.0000x reference)
#include <cuda_runtime.h>
#include <cuda_bf16.h>
#include <cstdint>
#include <cstddef>

// Problem constants
#define B_ 64
#define S_ 512
#define E_ 256
#define H_ 512

// Scan decomposition: 16 clusters x 8 CTAs; each cluster owns 4 batch rows,
// split into TWO independent 2-row sub-problems (pipelined). Each CTA owns
// 64 rows of W_hh in REGISTERS. h exchange: one cp.async.bulk per peer/lane.
#define BT_ 16       // batch tiles (clusters)
#define BC_ 4        // batch rows per cluster (2 subs x 2 lanes)
#define CL_ 8        // CTAs per cluster (j split: 8 * 64 = 512)
#define JL_ 64       // W_hh rows per CTA
#define HROW_ 544    // h floats per batch row: 8 blocks of (64 data + 4 pad)
#define HPS_ 1088    // per-sub per-parity h buffer: 2 rows * HROW_
#define RP2_ 132     // red pitch per ks block: 64 j * 2 lanes + 4 pad
                     // multiple of 4 (float4 stores) and ≡4 mod 32 (banks)

typedef unsigned long long u64;

// ---------------------------------------------------------------------------
// Packed fp32x2 helpers (Blackwell FFMA2 path: 2x fp32 throughput, full IEEE)
// ---------------------------------------------------------------------------
__device__ __forceinline__ u64 pack2(float lo, float hi) {
    u64 r; asm("mov.b64 %0, {%1, %2};" : "=l"(r) : "f"(lo), "f"(hi)); return r;
}
__device__ __forceinline__ u64 splat2(float x) {
    u64 r; asm("mov.b64 %0, {%1, %1};" : "=l"(r) : "f"(x)); return r;
}
__device__ __forceinline__ void fma2(u64& d, u64 a, u64 b) {
    asm("fma.rn.f32x2 %0, %1, %2, %0;" : "+l"(d) : "l"(a), "l"(b));
}
__device__ __forceinline__ void unpack2(u64 v, float& lo, float& hi) {
    asm("mov.b64 {%0, %1}, %2;" : "=f"(lo), "=f"(hi) : "l"(v));
}

// Fast tanh: 2 MUFU ops, abs error ~1e-7. Large |x| -> exp=inf -> 1.
__device__ __forceinline__ float fast_tanh(float x) {
    float ax = fabsf(x);
    float e  = __expf(ax + ax);
    float r  = 1.0f - __fdividef(2.0f, e + 1.0f);
    return copysignf(r, x);
}

// ---------------------------------------------------------------------------
// DSMEM / mbarrier primitives
// ---------------------------------------------------------------------------
__device__ __forceinline__ uint32_t smem_u32(const void* p) {
    uint32_t a;
    asm("{ .reg .u64 t; cvta.to.shared.u64 t, %1; cvt.u32.u64 %0, t; }"
        : "=r"(a) : "l"(p));
    return a;
}
__device__ __forceinline__ uint32_t mapa_(uint32_t addr, uint32_t rank) {
    uint32_t r;
    asm("mapa.shared::cluster.u32 %0, %1, %2;" : "=r"(r) : "r"(addr), "r"(rank));
    return r;
}
__device__ __forceinline__ void mbar_init(uint32_t mbar, uint32_t count) {
    asm volatile("mbarrier.init.shared.b64 [%0], %1;" :: "r"(mbar), "r"(count) : "memory");
}
__device__ __forceinline__ void mbar_arrive_expect_tx(uint32_t mbar, uint32_t bytes) {
    asm volatile("mbarrier.arrive.expect_tx.shared.b64 _, [%0], %1;"
                 :: "r"(mbar), "r"(bytes) : "memory");
}
__device__ __forceinline__ void mbar_wait(uint32_t mbar, uint32_t parity) {
    asm volatile(
        "{\n\t"
        ".reg .pred P1;\n\t"
        "WAIT_LOOP_%=:\n\t"
        "mbarrier.try_wait.parity.acquire.cluster.shared::cta.b64 P1, [%0], %1, 0x989680;\n\t"
        "@P1 bra.uni WAIT_DONE_%=;\n\t"
        "bra.uni WAIT_LOOP_%=;\n\t"
        "WAIT_DONE_%=:\n\t"
        "}"
        :: "r"(mbar), "r"(parity) : "memory");
}
// Bulk DSMEM copy: local smem -> peer CTA smem, one tx-completion of `bytes`
// on the peer's mbarrier. Replaces per-value st.async (message-rate bound).
__device__ __forceinline__ void bulk_dsmem(uint32_t dst_cluster, uint32_t src_cta,
                                           uint32_t bytes, uint32_t rmbar_cluster) {
    asm volatile(
        "cp.async.bulk.shared::cluster.shared::cta.mbarrier::complete_tx::bytes "
        "[%0], [%1], %2, [%3];"
        :: "r"(dst_cluster), "r"(src_cta), "r"(bytes), "r"(rmbar_cluster) : "memory");
}
__device__ __forceinline__ void fence_proxy_async_() {
    asm volatile("fence.proxy.async.shared::cta;" ::: "memory");
}
#define CLUSTER_SYNC_() do { \
    asm volatile("barrier.cluster.arrive.aligned;" ::: "memory"); \
    asm volatile("barrier.cluster.wait.aligned;" ::: "memory"); \
} while (0)

// ---------------------------------------------------------------------------
// Device scratch (no allocations allowed)
// ---------------------------------------------------------------------------
__device__ float g_pre[(size_t)B_ * S_ * H_];   // pre-activations (reused per layer)
__device__ float g_y0[(size_t)B_ * S_ * H_];    // layer-0 outputs

// ---------------------------------------------------------------------------
// GEMM: C[m,n] = sum_k Arow(m)[k] * W[n,k] + ba[n] + bb[n]   (unchanged, proven)
// ---------------------------------------------------------------------------
__global__ void __launch_bounds__(256) gemm_tn_kernel(
    const float* __restrict__ A, const int* __restrict__ idx, int lda,
    const float* __restrict__ W, const float* __restrict__ ba,
    const float* __restrict__ bb, float* __restrict__ C, int N, int K)
{
    __shared__ __align__(16) float As[16][136];
    __shared__ __align__(16) float Bs[16][136];
    __shared__ int srcs[128];

    const int tid = threadIdx.x;
    const int m0 = blockIdx.y * 128;
    const int n0 = blockIdx.x * 128;

    if (idx != nullptr && tid < 128) srcs[tid] = idx[m0 + tid];
    __syncthreads();

    const int lm = tid >> 1;
    const int lk = (tid & 1) * 8;
    const float* arow = (idx != nullptr) ? (A + (size_t)srcs[lm] * (size_t)lda)
                                         : (A + (size_t)(m0 + lm) * (size_t)lda);
    const float* brow = W + (size_t)(n0 + lm) * (size_t)K;

    const int iy = tid >> 4;
    const int ix = tid & 15;

    u64 acc[8][4];
#pragma unroll
    for (int r = 0; r < 8; ++r)
#pragma unroll
        for (int c = 0; c < 4; ++c) acc[r][c] = 0ull;

    for (int k0 = 0; k0 < K; k0 += 16) {
        float4 av0 = *(const float4*)(arow + k0 + lk);
        float4 av1 = *(const float4*)(arow + k0 + lk + 4);
        float4 bv0 = *(const float4*)(brow + k0 + lk);
        float4 bv1 = *(const float4*)(brow + k0 + lk + 4);
        __syncthreads();
        As[lk + 0][lm] = av0.x; As[lk + 1][lm] = av0.y;
        As[lk + 2][lm] = av0.z; As[lk + 3][lm] = av0.w;
        As[lk + 4][lm] = av1.x; As[lk + 5][lm] = av1.y;
        As[lk + 6][lm] = av1.z; As[lk + 7][lm] = av1.w;
        Bs[lk + 0][lm] = bv0.x; Bs[lk + 1][lm] = bv0.y;
        Bs[lk + 2][lm] = bv0.z; Bs[lk + 3][lm] = bv0.w;
        Bs[lk + 4][lm] = bv1.x; Bs[lk + 5][lm] = bv1.y;
        Bs[lk + 6][lm] = bv1.z; Bs[lk + 7][lm] = bv1.w;
        __syncthreads();
#pragma unroll
        for (int k = 0; k < 16; ++k) {
            float4 a0 = *(const float4*)&As[k][iy * 8];
            float4 a1 = *(const float4*)&As[k][iy * 8 + 4];
            ulonglong2 bq0 = *(const ulonglong2*)&Bs[k][ix * 8];
            ulonglong2 bq1 = *(const ulonglong2*)&Bs[k][ix * 8 + 4];
            u64 s;
            s = splat2(a0.x);
            fma2(acc[0][0], s, bq0.x); fma2(acc[0][1], s, bq0.y);
            fma2(acc[0][2], s, bq1.x); fma2(acc[0][3], s, bq1.y);
            s = splat2(a0.y);
            fma2(acc[1][0], s, bq0.x); fma2(acc[1][1], s, bq0.y);
            fma2(acc[1][2], s, bq1.x); fma2(acc[1][3], s, bq1.y);
            s = splat2(a0.z);
            fma2(acc[2][0], s, bq0.x); fma2(acc[2][1], s, bq0.y);
            fma2(acc[2][2], s, bq1.x); fma2(acc[2][3], s, bq1.y);
            s = splat2(a0.w);
            fma2(acc[3][0], s, bq0.x); fma2(acc[3][1], s, bq0.y);
            fma2(acc[3][2], s, bq1.x); fma2(acc[3][3], s, bq1.y);
            s = splat2(a1.x);
            fma2(acc[4][0], s, bq0.x); fma2(acc[4][1], s, bq0.y);
            fma2(acc[4][2], s, bq1.x); fma2(acc[4][3], s, bq1.y);
            s = splat2(a1.y);
            fma2(acc[5][0], s, bq0.x); fma2(acc[5][1], s, bq0.y);
            fma2(acc[5][2], s, bq1.x); fma2(acc[5][3], s, bq1.y);
            s = splat2(a1.z);
            fma2(acc[6][0], s, bq0.x); fma2(acc[6][1], s, bq0.y);
            fma2(acc[6][2], s, bq1.x); fma2(acc[6][3], s, bq1.y);
            s = splat2(a1.w);
            fma2(acc[7][0], s, bq0.x); fma2(acc[7][1], s, bq0.y);
            fma2(acc[7][2], s, bq1.x); fma2(acc[7][3], s, bq1.y);
        }
    }

    const int n = n0 + ix * 8;
    float bias[8];
#pragma unroll
    for (int c = 0; c < 8; ++c) bias[c] = ba[n + c] + bb[n + c];

#pragma unroll
    for (int r = 0; r < 8; ++r) {
        float v[8];
#pragma unroll
        for (int c = 0; c < 4; ++c) unpack2(acc[r][c], v[2 * c], v[2 * c + 1]);
        float4 o0 = make_float4(v[0] + bias[0], v[1] + bias[1], v[2] + bias[2], v[3] + bias[3]);
        float4 o1 = make_float4(v[4] + bias[4], v[5] + bias[5], v[6] + bias[6], v[7] + bias[7]);
        float* crow = C + (size_t)(m0 + iy * 8 + r) * (size_t)N + n;
        *(float4*)(crow)     = o0;
        *(float4*)(crow + 4) = o1;
    }
}

// ---------------------------------------------------------------------------
// Recurrent scan, pipelined over two independent 2-batch sub-problems.
//   phase(sub s): wait h_s(t-1) -> matvec -> reduce -> finalize:
//     tanh -> STS into staging -> bar.sync(sub) -> ONE elected thread issues
//     2 cp.async.bulk (256 B each) per peer CTA -> 16 barrier tx/step
//     (was 1024 scalar st.async tx -> barrier-update serialization bound).
// ---------------------------------------------------------------------------
__global__ void __launch_bounds__(256, 1) __cluster_dims__(CL_, 1, 1)
rnn_scan_kernel(const float* __restrict__ pre, const float* __restrict__ Whh,
                float* __restrict__ y, float* __restrict__ hlast)
{
    __shared__ __align__(16) float h_sh[2][2][HPS_];    // [sub][parity][2 rows * 544]
    __shared__ __align__(16) float red[2][8 * RP2_];    // [sub][ks][64 j * 2 lanes (+pad)]
    __shared__ __align__(16) float stage[2][2][128];    // [sub][parity][lane*64 + j]
    __shared__ __align__(8) u64 bars[2][2];             // [sub][parity]

    const int tid  = threadIdx.x;
    const int rank = blockIdx.x;   // 0..7  (j slice)
    const int bt   = blockIdx.y;   // 0..15 (batch tile)
    const int jg   = tid >> 3;     // 0..31 (2 j-rows each)
    const int ks   = tid & 7;      // 0..7  (64-k slice)

    uint32_t barAddr[2][2];
#pragma unroll
    for (int s = 0; s < 2; ++s) {
        barAddr[s][0] = smem_u32(&bars[s][0]);
        barAddr[s][1] = smem_u32(&bars[s][1]);
    }

    if (tid == 0) {
#pragma unroll
        for (int s = 0; s < 2; ++s) {
            mbar_init(barAddr[s][0], 1);
            mbar_init(barAddr[s][1], 1);
            mbar_arrive_expect_tx(barAddr[s][1], 4096);   // first use: h_1 at t=1
            mbar_arrive_expect_tx(barAddr[s][0], 4096);   // first use: h_2 at t=2
        }
    }
    // h_0 = 0 in parity-0 buffers; parity-1 fully overwritten by bulk copies
    for (int i = tid; i < HPS_; i += 256) { h_sh[0][0][i] = 0.f; h_sh[1][0][i] = 0.f; }
    __syncthreads();
    CLUSTER_SYNC_();   // all CTAs' mbarriers live before any bulk copy

    // --- W slice into registers: rows {2jg, 2jg+1}, k in [ks*64, ks*64+64) ---
    u64 wA[32], wB[32];
    {
        const float4* wa = (const float4*)(Whh + (size_t)(rank * JL_ + 2 * jg) * H_ + ks * 64);
        const float4* wb = (const float4*)(Whh + (size_t)(rank * JL_ + 2 * jg + 1) * H_ + ks * 64);
#pragma unroll
        for (int i = 0; i < 16; ++i) {
            float4 va = __ldg(wa + i);
            float4 vb = __ldg(wb + i);
            wA[2 * i] = pack2(va.x, va.y); wA[2 * i + 1] = pack2(va.z, va.w);
            wB[2 * i] = pack2(vb.x, vb.y); wB[2 * i + 1] = pack2(vb.z, vb.w);
        }
    }

    // --- finalize identity: each thread owns ONE h value of ONE sub ---
    const int sub   = tid >> 7;        // which sub-problem this thread finalizes
    const int fj    = tid & 63;        // j row within CTA slice
    const int fb    = (tid >> 6) & 1;  // batch lane within sub
    const int batch = bt * BC_ + sub * 2 + fb;
    const size_t pbase = ((size_t)batch * S_) * H_ + rank * JL_ + fj;
    const bool elected = (fj == 0 && fb == 0);   // tid == sub*128

    // loop-invariant local addresses for the elected sender
    const uint32_t dst0_base = smem_u32(&h_sh[sub][0][rank * 68]);        // lane-0 block
    const uint32_t src_base  = smem_u32(&stage[sub][0][0]);

    for (int t = 0; t < S_; ++t) {
        const int q = t & 1;
        const int qn = (t + 1) & 1;
        const uint32_t poff = qn ? (uint32_t)(HPS_ * 4) : 0u;   // next-parity h offset
        const uint32_t boff = qn ? 8u : 0u;                     // next-parity bar offset

#pragma unroll
        for (int s = 0; s < 2; ++s) {
            // prefetch pre[t] (only this phase's senders) before the wait
            float p = 0.f;
            if (sub == s) p = __ldg(pre + pbase + (size_t)t * H_);

            if (t > 0) {
                mbar_wait(barAddr[s][q], ((unsigned)(t - 1) >> 1) & 1);
                if (tid == 0 && t + 2 < S_)
                    mbar_arrive_expect_tx(barAddr[s][q], 4096);   // re-arm for t+2
            }

            // --- matvec: 2 j-rows x 2 lanes over this thread's 64 k ---
            const float* hb = h_sh[s][q];
            const char* h0 = (const char*)(hb + ks * 68);            // lane 0
            const char* h1 = (const char*)(hb + HROW_ + ks * 68);    // lane 1
            u64 a00 = 0, a01 = 0, a10 = 0, a11 = 0;  // [rowA/B][lane0/1]
#pragma unroll
            for (int ii = 0; ii < 16; ++ii) {
                ulonglong2 x0 = *(const ulonglong2*)(h0 + ii * 16);
                ulonglong2 x1 = *(const ulonglong2*)(h1 + ii * 16);
                const u64 wa0 = wA[2 * ii], wa1 = wA[2 * ii + 1];
                const u64 wb0 = wB[2 * ii], wb1 = wB[2 * ii + 1];
                fma2(a00, wa0, x0.x); fma2(a00, wa1, x0.y);
                fma2(a01, wa0, x1.x); fma2(a01, wa1, x1.y);
                fma2(a10, wb0, x0.x); fma2(a10, wb1, x0.y);
                fma2(a11, wb0, x1.x); fma2(a11, wb1, x1.y);
            }

            // fold k-pair halves -> 4 scalars; layout word = row*2 + lane
            float lo, hi;
            float4 v4;
            unpack2(a00, lo, hi); v4.x = lo + hi;   // row 2jg,   lane 0
            unpack2(a01, lo, hi); v4.y = lo + hi;   // row 2jg,   lane 1
            unpack2(a10, lo, hi); v4.z = lo + hi;   // row 2jg+1, lane 0
            unpack2(a11, lo, hi); v4.w = lo + hi;   // row 2jg+1, lane 1
            *(float4*)&red[s][ks * RP2_ + 4 * jg] = v4;   // RP2_ multiple of 4 -> aligned
            __syncthreads();

            // --- finalize: this sub's 128 owner threads ---
            if (sub == s) {
                float acc = p;
#pragma unroll
                for (int g = 0; g < 8; ++g) acc += red[s][g * RP2_ + fj * 2 + fb];
                const float v = fast_tanh(acc);
                y[pbase + (size_t)t * H_] = v;
                if (t == S_ - 1) {
                    hlast[(size_t)batch * H_ + rank * JL_ + fj] = v;
                } else {
                    stage[s][qn][fb * 64 + fj] = v;
                    // all 128 staging stores visible, then one thread ships bulk
                    asm volatile("bar.sync %0, 128;" :: "r"(1 + s) : "memory");
                    if (elected) {
                        fence_proxy_async_();
                        const uint32_t src0 = src_base + (uint32_t)(qn * 512);
                        const uint32_t src1 = src0 + 256;
                        const uint32_t d0   = dst0_base + poff;          // lane-0 dst
                        const uint32_t d1   = d0 + (uint32_t)(HROW_ * 4); // lane-1 dst
                        const uint32_t bl   = barAddr[s][0] + boff;
#pragma unroll
                        for (uint32_t c = 0; c < CL_; ++c) {
                            const uint32_t rb = mapa_(bl, c);
                            bulk_dsmem(mapa_(d0, c), src0, 256, rb);
                            bulk_dsmem(mapa_(d1, c), src1, 256, rb);
                        }
                    }
                }
            }
        }
    }
}

// ---------------------------------------------------------------------------
// Launch
// Inputs: src, emb, W_ih0, W_hh0, b_ih0, b_hh0, W_ih1, W_hh1, b_ih1, b_hh1
// Output: y1 [B,S,H] followed by hidden [2,B,H]
// ---------------------------------------------------------------------------
extern "C" void kernel_launch(void* const* d_in, const int* in_sizes, int n_in,
                              void* d_out, int out_size)
{
    (void)in_sizes; (void)n_in; (void)out_size;
    const int*   src  = (const int*)d_in[0];
    const float* emb  = (const float*)d_in[1];
    const float* Wih0 = (const float*)d_in[2];
    const float* Whh0 = (const float*)d_in[3];
    const float* bih0 = (const float*)d_in[4];
    const float* bhh0 = (const float*)d_in[5];
    const float* Wih1 = (const float*)d_in[6];
    const float* Whh1 = (const float*)d_in[7];
    const float* bih1 = (const float*)d_in[8];
    const float* bhh1 = (const float*)d_in[9];

    float* out = (float*)d_out;
    float* y1  = out;
    float* hid = out + (size_t)B_ * S_ * H_;

    float *pre = nullptr, *y0 = nullptr;
    cudaGetSymbolAddress((void**)&pre, g_pre);
    cudaGetSymbolAddress((void**)&y0,  g_y0);

    const dim3 gemm_blk(256);
    const dim3 scan_blk(256);
    const dim3 gemm_grid(H_ / 128, (B_ * S_) / 128);
    const dim3 scan_grid(CL_, BT_);

    // Layer 0: fused embedding-gather GEMM -> pre, then scan -> y0, h_last0
    gemm_tn_kernel<<<gemm_grid, gemm_blk>>>(emb, src, E_, Wih0, bih0, bhh0, pre, H_, E_);
    rnn_scan_kernel<<<scan_grid, scan_blk>>>(pre, Whh0, y0, hid);

    // Layer 1: plain GEMM -> pre (reused), then scan -> y1 (d_out), h_last1
    gemm_tn_kernel<<<gemm_grid, gemm_blk>>>(y0, nullptr, H_, Wih1, bih1, bhh1, pre, H_, H_);
    rnn_scan_kernel<<<scan_grid, scan_blk>>>(pre, Whh1, y1, hid + (size_t)B_ * H_);
}